// round 12
// baseline (speedup 1.0000x reference)
#include <cuda_runtime.h>
#include <math.h>

#define Cn 4096
#define Vn 32000
#define Hn 256
#define Dn 128
#define Nb 16
#define Tt 256
#define NBLK 128

// ---------------- device scratch (static) ----------------
__device__ float g_Xn[Vn * Hn];        // normalized-row staging (max V rows)
__device__ float g_t1[Cn * Hn];
__device__ float g_f1[Cn * Hn];
__device__ float g_t2[Cn * Hn];
__device__ float g_ft[Cn * Hn];
__device__ float g_Eyn[Cn * Dn];       // features of next_state_emb
__device__ float g_Exn[Cn * Dn];       // features of state_emb (row-normalized: ExnN·Sn = 1)
__device__ float g_Ext[Cn * Dn];       // features of terminal-MLP out (row-normalized by Se)
__device__ float g_Ele[Vn * Dn];       // features of terminal_emb
__device__ float g_Sn[Dn];
__device__ float g_Se[Dn];
__device__ float g_Exs[Dn];
__device__ float g_buf[3][Nb][Dn];     // rotating G state buffers
__device__ unsigned g_bar;
__device__ volatile unsigned g_gen;

// ---------------- zero / reset ----------------
__global__ __launch_bounds__(128) void kzero() {
    int i = threadIdx.x;
    if (i < Dn) { g_Sn[i] = 0.f; g_Se[i] = 0.f; }
    if (i == 0) { g_bar = 0u; g_gen = 0u; }
}

// ------------- generic tiled GEMM: Out = epi(A[M,K]@W[K,N]) -------------
// mode 1: relu(+bias); 2: relu(+bias)+R; 3: exp(x-0.5)
__global__ __launch_bounds__(256) void kgemm(const float* __restrict__ A,
                                             const float* __restrict__ W,
                                             const float* __restrict__ bias,
                                             const float* __restrict__ R,
                                             float* __restrict__ Out,
                                             int M, int N, int K, int mode) {
    __shared__ float As[16][68];
    __shared__ float Ws[16][68];
    int tid = threadIdx.x;
    int m0 = blockIdx.x * 64, n0 = blockIdx.y * 64;
    int ar = tid >> 2, ak = (tid & 3) * 4;
    int wk = tid >> 4, wn = (tid & 15) * 4;
    int ty = tid >> 4, tx = tid & 15;
    float acc[4][4] = {};
    for (int kt = 0; kt < K; kt += 16) {
        float4 av = *(const float4*)(A + (size_t)(m0 + ar) * K + kt + ak);
        As[ak + 0][ar] = av.x; As[ak + 1][ar] = av.y;
        As[ak + 2][ar] = av.z; As[ak + 3][ar] = av.w;
        *(float4*)&Ws[wk][wn] = *(const float4*)(W + (size_t)(kt + wk) * N + n0 + wn);
        __syncthreads();
#pragma unroll
        for (int k = 0; k < 16; k++) {
            float a[4], b[4];
            *(float4*)a = *(const float4*)&As[k][ty * 4];
            *(float4*)b = *(const float4*)&Ws[k][tx * 4];
#pragma unroll
            for (int i = 0; i < 4; i++)
#pragma unroll
                for (int j = 0; j < 4; j++) acc[i][j] += a[i] * b[j];
        }
        __syncthreads();
    }
#pragma unroll
    for (int i = 0; i < 4; i++) {
        int m = m0 + ty * 4 + i;
#pragma unroll
        for (int j = 0; j < 4; j++) {
            int n = n0 + tx * 4 + j;
            float v = acc[i][j];
            if (mode == 1 || mode == 2) v = fmaxf(v + bias[n], 0.f);
            if (mode == 2) v += R[(size_t)m * N + n];
            if (mode == 3) v = expf(v - 0.5f);
            Out[(size_t)m * N + n] = v;
        }
    }
}

// ------------- row l2-normalize -------------
__global__ __launch_bounds__(256) void krownorm(const float* __restrict__ X,
                                                float* __restrict__ Xn) {
    int r = blockIdx.x, tid = threadIdx.x;
    __shared__ float red[8];
    float v = X[(size_t)r * Hn + tid];
    float ss = v * v;
#pragma unroll
    for (int o = 16; o; o >>= 1) ss += __shfl_xor_sync(~0u, ss, o);
    if ((tid & 31) == 0) red[tid >> 5] = ss;
    __syncthreads();
    float tot = 0.f;
#pragma unroll
    for (int i = 0; i < 8; i++) tot += red[i];
    Xn[(size_t)r * Hn + tid] = v * rsqrtf(tot);
}

// ------------- column sums -------------
__global__ __launch_bounds__(128) void kcolsum(const float* __restrict__ E, int rows,
                                               float* __restrict__ S) {
    int d = threadIdx.x;
    float acc = 0.f;
    for (int r = blockIdx.x; r < rows; r += gridDim.x) acc += E[(size_t)r * Dn + d];
    atomicAdd(&S[d], acc);
}

// ------------- row normalize: E[r,:] /= (E[r,:]·S) -------------
__global__ __launch_bounds__(128) void krowdiv(float* __restrict__ E,
                                               const float* __restrict__ S) {
    int r = blockIdx.x, tid = threadIdx.x;
    __shared__ float red[4];
    float v = E[(size_t)r * Dn + tid];
    float p = v * S[tid];
#pragma unroll
    for (int o = 16; o; o >>= 1) p += __shfl_xor_sync(~0u, p, o);
    if ((tid & 31) == 0) red[tid >> 5] = p;
    __syncthreads();
    float u = red[0] + red[1] + red[2] + red[3];
    E[(size_t)r * Dn + tid] = v / u;
}

// ------------- start MLP + features of the single start vector -------------
__global__ __launch_bounds__(256) void kstartmlp(
    const float* se, const float* w0, const float* b0,
    const float* w1, const float* b1, const float* w2, const float* b2,
    const float* w3, const float* b3, const float* w4, const float* b4,
    const float* proj) {
    __shared__ float xs[256], Ab[256], Bb[256], Cb[256];
    __shared__ float red[8], sinv;
    int tid = threadIdx.x;
    xs[tid] = se[tid];
    __syncthreads();
    float acc = 0.f;
    for (int i = 0; i < 256; i++) acc += xs[i] * w0[i * 256 + tid];
    Ab[tid] = acc + b0[tid];
    __syncthreads();
    acc = 0.f;
    for (int i = 0; i < 256; i++) acc += Ab[i] * w1[i * 256 + tid];
    Bb[tid] = fmaxf(acc + b1[tid], 0.f);
    __syncthreads();
    acc = 0.f;
    for (int i = 0; i < 256; i++) acc += Bb[i] * w2[i * 256 + tid];
    Cb[tid] = fmaxf(acc + b2[tid], 0.f) + Ab[tid];
    __syncthreads();
    acc = 0.f;
    for (int i = 0; i < 256; i++) acc += Cb[i] * w3[i * 256 + tid];
    __syncthreads();
    Bb[tid] = fmaxf(acc + b3[tid], 0.f);
    __syncthreads();
    acc = 0.f;
    for (int i = 0; i < 256; i++) acc += Bb[i] * w4[i * 256 + tid];
    Ab[tid] = fmaxf(acc + b4[tid], 0.f) + Cb[tid];
    __syncthreads();
    float ss = Ab[tid] * Ab[tid];
#pragma unroll
    for (int o = 16; o; o >>= 1) ss += __shfl_xor_sync(~0u, ss, o);
    if ((tid & 31) == 0) red[tid >> 5] = ss;
    __syncthreads();
    if (tid == 0) {
        float t = 0.f;
        for (int i = 0; i < 8; i++) t += red[i];
        sinv = rsqrtf(t);
    }
    __syncthreads();
    if (tid < 128) {
        float a2 = 0.f;
        for (int i = 0; i < 256; i++) a2 += Ab[i] * proj[i * 128 + tid];
        g_Exs[tid] = expf(a2 * sinv - 0.5f);
    }
}

// =========== persistent recursion kernel: all 256 HMM steps ===========
// 128 blocks x 512 threads (16 warps/SM), software grid barrier.
#define GRIDBAR()                                                              \
    do {                                                                       \
        __threadfence();                                                       \
        __syncthreads();                                                       \
        if (tid == 0) {                                                        \
            if (atomicAdd(&g_bar, 1u) == NBLK - 1u) {                          \
                atomicExch(&g_bar, 0u);                                        \
                __threadfence();                                               \
                atomicAdd((unsigned*)&g_gen, 1u);                              \
            } else {                                                           \
                while (g_gen <= gen) __nanosleep(64);                          \
            }                                                                  \
        }                                                                      \
        __syncthreads();                                                       \
        gen++;                                                                 \
    } while (0)

__global__ __launch_bounds__(512, 1) void krec(const int* __restrict__ text,
                                               float* __restrict__ out) {
    __shared__ float Gs[Nb][Dn];
    __shared__ float Egs[Nb][Dn];
    __shared__ float Ash[Nb][32];
    __shared__ float zsh[Nb];
    __shared__ float snS[Dn];
    int tid = threadIdx.x;
    int blk = blockIdx.x;
    int w = tid >> 5, lane = tid & 31;
    int cl = tid >> 4, q = tid & 15;        // 32 states/block, 16 lanes/state
    int dd = tid & 127, half = tid >> 7;    // G'-phase: 4 outputs, fixed d
    unsigned gen = 0;

    // persistent operands: split-half layout -> 2-way-max LDS conflicts
    float4 ar0, ar1, br0, br1;
    float xn[32];
    {
        const float* ap = g_Ext + (size_t)(blk * 32 + cl) * Dn;
        const float* bp = g_Eyn + (size_t)(blk * 32 + cl) * Dn;
        ar0 = *(const float4*)(ap + q * 4);
        ar1 = *(const float4*)(ap + 64 + q * 4);
        br0 = *(const float4*)(bp + q * 4);
        br1 = *(const float4*)(bp + 64 + q * 4);
#pragma unroll
        for (int c = 0; c < 32; c++) xn[c] = g_Exn[(size_t)(blk * 32 + c) * Dn + dd];
    }
    if (tid < Dn) snS[tid] = g_Sn[tid];

    // init rotating buffers: buf0 = Exs replicated, buf1 = 0
    if (tid < 16) {
        int ib = blk * 16 + tid;
        __stcg(&((float*)g_buf[0])[ib], g_Exs[ib & 127]);
        __stcg(&((float*)g_buf[1])[ib], 0.f);
    }
    float evAcc = 0.f;
    GRIDBAR();

    float* bufp0 = (float*)g_buf[0];
    float* bufp1 = (float*)g_buf[1];
    float* bufp2 = (float*)g_buf[2];

    // prefetch token features for t=0
    float egv[4];
#pragma unroll
    for (int k = 0; k < 4; k++) {
        int i = k * 512 + tid, n = i >> 7, d = i & 127;
        int tk = __ldg(&text[n * Tt + 0]);
        egv[k] = __ldg(&g_Ele[(size_t)tk * Dn + d]);
    }

    for (int t = 0; t < Tt; t++) {
        const float* Gcur = bufp0;
        float* Gnext = bufp1;
        float* Gz = bufp2;

        // z[n] = G[n,:]·Sn ; ghat = G/z  (warp w owns batch w, fully warp-local)
        {
            float4 g = __ldcg((const float4*)(Gcur + w * Dn + lane * 4));
            float4 s4 = *(const float4*)&snS[lane * 4];
            float z = g.x * s4.x + g.y * s4.y + g.z * s4.z + g.w * s4.w;
#pragma unroll
            for (int o = 16; o; o >>= 1) z += __shfl_xor_sync(~0u, z, o);
            if (lane == 0) zsh[w] = z;
            float inv = 1.f / z;
            g.x *= inv; g.y *= inv; g.z *= inv; g.w *= inv;
            *(float4*)&Gs[w][lane * 4] = g;
        }
        // stage token features
#pragma unroll
        for (int k = 0; k < 4; k++) ((float*)Egs)[k * 512 + tid] = egv[k];
        __syncthreads();
        if (blk == 0 && tid < 16 && t > 0) evAcc += logf(zsh[tid]);

        // A[n,c] = (ExtN_c·Ele_n) * (ghat_n·Eyn_c)
#pragma unroll
        for (int n = 0; n < Nb; n++) {
            float4 e0 = *(const float4*)&Egs[n][q * 4];
            float4 e1 = *(const float4*)&Egs[n][64 + q * 4];
            float4 g0 = *(const float4*)&Gs[n][q * 4];
            float4 g1 = *(const float4*)&Gs[n][64 + q * 4];
            float eo = ar0.x * e0.x + ar0.y * e0.y + ar0.z * e0.z + ar0.w * e0.w
                     + ar1.x * e1.x + ar1.y * e1.y + ar1.z * e1.z + ar1.w * e1.w;
            float mo = br0.x * g0.x + br0.y * g0.y + br0.z * g0.z + br0.w * g0.w
                     + br1.x * g1.x + br1.y * g1.y + br1.z * g1.z + br1.w * g1.w;
#pragma unroll
            for (int o = 8; o; o >>= 1) {
                eo += __shfl_xor_sync(~0u, eo, o);
                mo += __shfl_xor_sync(~0u, mo, o);
            }
            if (q == 0) Ash[n][cl] = eo * mo;
        }
        __syncthreads();

        // G'[n,d] += A[n, block slice] @ ExnN[block slice, d]
#pragma unroll
        for (int k = 0; k < 4; k++) {
            int n = k * 4 + half;
            float acc = 0.f;
            const float* arow = Ash[n];
#pragma unroll
            for (int c = 0; c < 32; c++) acc += arow[c] * xn[c];
            atomicAdd(&Gnext[n * Dn + dd], acc);
        }
        // zero the buffer that becomes Gnext at t+1
        if (tid < 16) __stcg(&Gz[blk * 16 + tid], 0.f);

        // prefetch next step's token features (hidden under the barrier)
        if (t + 1 < Tt) {
#pragma unroll
            for (int k = 0; k < 4; k++) {
                int i = k * 512 + tid, n = i >> 7, d = i & 127;
                int tk = __ldg(&text[n * Tt + t + 1]);
                egv[k] = __ldg(&g_Ele[(size_t)tk * Dn + d]);
            }
        }

        GRIDBAR();
        float* tmp = bufp0; bufp0 = bufp1; bufp1 = bufp2; bufp2 = tmp;
    }

    // finalize: block 0 adds log Z of the last step and reduces evidence
    if (blk == 0) {
        const float* Gf = bufp0;
        float4 g = __ldcg((const float4*)(Gf + w * Dn + lane * 4));
        float4 s4 = *(const float4*)&snS[lane * 4];
        float z = g.x * s4.x + g.y * s4.y + g.z * s4.z + g.w * s4.w;
#pragma unroll
        for (int o = 16; o; o >>= 1) z += __shfl_xor_sync(~0u, z, o);
        if (lane == 0) zsh[w] = z;
        __syncthreads();
        if (tid < 16) evAcc += logf(zsh[tid]);
        if (w == 0) {
#pragma unroll
            for (int o = 8; o; o >>= 1) evAcc += __shfl_xor_sync(~0u, evAcc, o);
            if (tid == 0) out[0] = evAcc;
        }
    }
}

extern "C" void kernel_launch(void* const* d_in, const int* in_sizes, int n_in,
                              void* d_out, int out_size) {
    (void)n_in; (void)out_size;
    const float *se, *sw0, *sb0, *sw1, *sb1, *sw2, *sb2, *sw3, *sb3, *sw4, *sb4;
    const float *state_emb, *next_state_emb, *pre_emb;
    const float *tw1, *tb1, *tw2, *tb2, *tw3, *tb3, *tw4, *tb4, *term_emb, *proj;
    const int* text;
    if (in_sizes[0] == Hn) {
        se  = (const float*)d_in[0];
        sw0 = (const float*)d_in[1];  sb0 = (const float*)d_in[2];
        sw1 = (const float*)d_in[3];  sb1 = (const float*)d_in[4];
        sw2 = (const float*)d_in[5];  sb2 = (const float*)d_in[6];
        sw3 = (const float*)d_in[7];  sb3 = (const float*)d_in[8];
        sw4 = (const float*)d_in[9];  sb4 = (const float*)d_in[10];
        state_emb = (const float*)d_in[11];
        next_state_emb = (const float*)d_in[12];
        pre_emb = (const float*)d_in[13];
        tw1 = (const float*)d_in[14]; tb1 = (const float*)d_in[15];
        tw2 = (const float*)d_in[16]; tb2 = (const float*)d_in[17];
        tw3 = (const float*)d_in[18]; tb3 = (const float*)d_in[19];
        tw4 = (const float*)d_in[20]; tb4 = (const float*)d_in[21];
        term_emb = (const float*)d_in[22];
        proj = (const float*)d_in[23];
        text = (const int*)d_in[24];
    } else {
        text = (const int*)d_in[0];
        se  = (const float*)d_in[2];
        sw0 = (const float*)d_in[3];  sb0 = (const float*)d_in[4];
        sw1 = (const float*)d_in[5];  sb1 = (const float*)d_in[6];
        sw2 = (const float*)d_in[7];  sb2 = (const float*)d_in[8];
        sw3 = (const float*)d_in[9];  sb3 = (const float*)d_in[10];
        sw4 = (const float*)d_in[11]; sb4 = (const float*)d_in[12];
        tw1 = (const float*)d_in[13]; tb1 = (const float*)d_in[14];
        tw2 = (const float*)d_in[15]; tb2 = (const float*)d_in[16];
        tw3 = (const float*)d_in[17]; tb3 = (const float*)d_in[18];
        tw4 = (const float*)d_in[19]; tb4 = (const float*)d_in[20];
        state_emb = (const float*)d_in[21];
        next_state_emb = (const float*)d_in[22];
        pre_emb = (const float*)d_in[23];
        term_emb = (const float*)d_in[24];
        proj = (const float*)d_in[25];
    }

    float *pXn, *pT1, *pF1, *pT2, *pFt, *pEyn, *pExn, *pExt, *pEle, *pSn, *pSe;
    cudaGetSymbolAddress((void**)&pXn, g_Xn);
    cudaGetSymbolAddress((void**)&pT1, g_t1);
    cudaGetSymbolAddress((void**)&pF1, g_f1);
    cudaGetSymbolAddress((void**)&pT2, g_t2);
    cudaGetSymbolAddress((void**)&pFt, g_ft);
    cudaGetSymbolAddress((void**)&pEyn, g_Eyn);
    cudaGetSymbolAddress((void**)&pExn, g_Exn);
    cudaGetSymbolAddress((void**)&pExt, g_Ext);
    cudaGetSymbolAddress((void**)&pEle, g_Ele);
    cudaGetSymbolAddress((void**)&pSn, g_Sn);
    cudaGetSymbolAddress((void**)&pSe, g_Se);

    kzero<<<1, 128>>>();

    // terminal MLP: two ResLayers on preterminal_emb
    kgemm<<<dim3(Cn / 64, 4), 256>>>(pre_emb, tw1, tb1, nullptr, pT1, Cn, Hn, Hn, 1);
    kgemm<<<dim3(Cn / 64, 4), 256>>>(pT1, tw2, tb2, pre_emb, pF1, Cn, Hn, Hn, 2);
    kgemm<<<dim3(Cn / 64, 4), 256>>>(pF1, tw3, tb3, nullptr, pT2, Cn, Hn, Hn, 1);
    kgemm<<<dim3(Cn / 64, 4), 256>>>(pT2, tw4, tb4, pF1, pFt, Cn, Hn, Hn, 2);

    // features
    krownorm<<<Cn, 256>>>(next_state_emb, pXn);
    kgemm<<<dim3(Cn / 64, 2), 256>>>(pXn, proj, nullptr, nullptr, pEyn, Cn, Dn, Hn, 3);
    kcolsum<<<256, 128>>>(pEyn, Cn, pSn);

    krownorm<<<Cn, 256>>>(state_emb, pXn);
    kgemm<<<dim3(Cn / 64, 2), 256>>>(pXn, proj, nullptr, nullptr, pExn, Cn, Dn, Hn, 3);
    krowdiv<<<Cn, 128>>>(pExn, pSn);   // ExnN: rows sum to 1 against Sn

    krownorm<<<Cn, 256>>>(pFt, pXn);
    kgemm<<<dim3(Cn / 64, 2), 256>>>(pXn, proj, nullptr, nullptr, pExt, Cn, Dn, Hn, 3);

    krownorm<<<Vn, 256>>>(term_emb, pXn);
    kgemm<<<dim3(Vn / 64, 2), 256>>>(pXn, proj, nullptr, nullptr, pEle, Vn, Dn, Hn, 3);
    kcolsum<<<256, 128>>>(pEle, Vn, pSe);
    krowdiv<<<Cn, 128>>>(pExt, pSe);   // ExtN

    kstartmlp<<<1, 256>>>(se, sw0, sb0, sw1, sb1, sw2, sb2, sw3, sb3, sw4, sb4, proj);

    // the whole 256-step recursion in ONE launch
    krec<<<NBLK, 512>>>(text, (float*)d_out);
}